// round 1
// baseline (speedup 1.0000x reference)
#include <cuda_runtime.h>
#include <math.h>
#include <stdint.h>

// ---------------- model constants ----------------
#define B_    2
#define N_    1024
#define D_    256
#define H_    8
#define DH_   32
#define K_    4
#define IN_   1024
#define V_    32000
#define CK_   3
#define MAXL_ 8
#define TRUNC_ 4
#define BN_   (B_ * N_)

// ---------------- scratch (device globals, no allocs) ----------------
__device__ float g_X  [BN_ * D_];
__device__ float g_Q  [BN_ * D_];
__device__ float g_Hc [BN_ * D_];
__device__ float g_pq [BN_ * D_];
__device__ float g_pk [BN_ * D_];
__device__ float g_v  [BN_ * D_];
__device__ float g_cmv[BN_ * D_];
__device__ float g_hn [BN_ * D_];
__device__ float g_gu [BN_ * 2 * IN_];
__device__ float g_hf [BN_ * IN_];
__device__ float g_hc2[BN_ * IN_];
__device__ float g_qn [BN_ * D_];

// ---------------- helpers ----------------
__device__ __forceinline__ float blockReduceSum256(float v) {
    __shared__ float sh[8];
    int lane = threadIdx.x & 31;
    int wid  = threadIdx.x >> 5;
#pragma unroll
    for (int o = 16; o > 0; o >>= 1) v += __shfl_down_sync(0xffffffffu, v, o);
    __syncthreads();               // protect sh reuse across calls
    if (lane == 0) sh[wid] = v;
    __syncthreads();
    float t = 0.f;
#pragma unroll
    for (int i = 0; i < 8; i++) t += sh[i];
    return t;
}

// ---------------- embedding + positional ----------------
__global__ void embed_kernel(const int* __restrict__ ids,
                             const float* __restrict__ emb,
                             const float* __restrict__ pos,
                             float* __restrict__ X) {
    int row = blockIdx.x;          // 0..BN_-1
    int d   = threadIdx.x;         // 0..255
    int n   = row & (N_ - 1);
    int id  = ids[row];
    X[(size_t)row * D_ + d] = emb[(size_t)id * D_ + d] + pos[(size_t)n * D_ + d];
}

// ---------------- layernorm (optional residual add + second output) ----------------
__global__ void ln_kernel(const float* __restrict__ in,
                          const float* __restrict__ w,
                          const float* __restrict__ b,
                          const float* __restrict__ addX,
                          float* __restrict__ out,
                          float* __restrict__ out2) {
    int row = blockIdx.x;
    int d   = threadIdx.x;
    float x  = in[(size_t)row * D_ + d];
    float mu = blockReduceSum256(x) * (1.f / D_);
    float dx = x - mu;
    float var = blockReduceSum256(dx * dx) * (1.f / D_);
    float y = dx * rsqrtf(var + 1e-5f) * w[d] + b[d];
    if (addX) y += addX[(size_t)row * D_ + d];
    out[(size_t)row * D_ + d] = y;
    if (out2) out2[(size_t)row * D_ + d] = y;
}

// ---------------- tiled SGEMM: C = epi(A[MxK] @ B[KxN]) ----------------
// EPI: 0 = none, 1 = elu(x)+1, 2 = aux + softplus(dts[kidx])*x, 3 = aux + x
#define BM 64
#define BNT 64
#define BK 32

template <int EPI>
__global__ void __launch_bounds__(256)
gemm_kernel(const float* __restrict__ A, const float* __restrict__ Bm,
            float* __restrict__ C, int M, int N, int Kd,
            const float* __restrict__ aux, const float* __restrict__ dts, int kidx) {
    __shared__ float As[BK][BM + 4];   // stride 68 floats (16B aligned rows)
    __shared__ float Bs[BK][BNT];

    int tid = threadIdx.x;
    int tx  = tid & 15;    // n-dir (x4)
    int ty  = tid >> 4;    // m-dir (x4)
    int row0 = blockIdx.y * BM;
    int col0 = blockIdx.x * BNT;

    float acc[4][4];
#pragma unroll
    for (int i = 0; i < 4; i++)
#pragma unroll
        for (int j = 0; j < 4; j++) acc[i][j] = 0.f;

    int ktiles = Kd / BK;
    for (int kt = 0; kt < ktiles; kt++) {
        // A tile: 64 rows x 32 cols = 512 float4, 2 per thread (transposed store)
#pragma unroll
        for (int it = 0; it < 2; it++) {
            int flat = it * 256 + tid;
            int m  = flat >> 3;
            int kq = (flat & 7) << 2;
            float4 av = *(const float4*)(A + (size_t)(row0 + m) * Kd + kt * BK + kq);
            As[kq + 0][m] = av.x;
            As[kq + 1][m] = av.y;
            As[kq + 2][m] = av.z;
            As[kq + 3][m] = av.w;
        }
        // B tile: 32 rows x 64 cols = 512 float4, 2 per thread
#pragma unroll
        for (int it = 0; it < 2; it++) {
            int flat = it * 256 + tid;
            int kk = flat >> 4;
            int nq = (flat & 15) << 2;
            *(float4*)(&Bs[kk][nq]) =
                *(const float4*)(Bm + (size_t)(kt * BK + kk) * N + col0 + nq);
        }
        __syncthreads();
#pragma unroll
        for (int kk = 0; kk < BK; kk++) {
            float4 a4 = *(const float4*)(&As[kk][ty * 4]);
            float4 b4 = *(const float4*)(&Bs[kk][tx * 4]);
            float av[4] = {a4.x, a4.y, a4.z, a4.w};
            float bv[4] = {b4.x, b4.y, b4.z, b4.w};
#pragma unroll
            for (int i = 0; i < 4; i++)
#pragma unroll
                for (int j = 0; j < 4; j++) acc[i][j] = fmaf(av[i], bv[j], acc[i][j]);
        }
        __syncthreads();
    }

    float sp = 0.f;
    if (EPI == 2) sp = log1pf(expf(dts[kidx]));

#pragma unroll
    for (int i = 0; i < 4; i++) {
        int r = row0 + ty * 4 + i;
#pragma unroll
        for (int j = 0; j < 4; j++) {
            int c = col0 + tx * 4 + j;
            size_t o = (size_t)r * N + c;
            float x = acc[i][j];
            if (EPI == 0) {
                C[o] = x;
            } else if (EPI == 1) {
                C[o] = (x > 0.f) ? (x + 1.f) : expf(x);   // elu(x)+1
            } else if (EPI == 2) {
                C[o] = aux[o] + sp * x;
            } else {
                C[o] = aux[o] + x;
            }
        }
    }
}

// ---------------- attention: relu^2 kernel-attention, fused normalize & (C - v) ----------------
__global__ void __launch_bounds__(128)
attn_kernel(const float* __restrict__ pq_, const float* __restrict__ pk_,
            const float* __restrict__ v_, float* __restrict__ cmv) {
    int bh = blockIdx.x;
    int b  = bh >> 3;        // H_ = 8
    int h  = bh & 7;
    int n  = blockIdx.y * 128 + threadIdx.x;
    size_t qoff = (size_t)(b * N_ + n) * D_ + h * DH_;

    float q[DH_], acc[DH_];
#pragma unroll
    for (int j = 0; j < DH_; j++) { q[j] = pq_[qoff + j]; acc[j] = 0.f; }
    float s = 0.f;

    __shared__ float sk[64][DH_];
    __shared__ float sv[64][DH_];

    for (int mt = 0; mt < N_; mt += 64) {
        __syncthreads();
#pragma unroll
        for (int it = 0; it < 4; it++) {
            int flat = it * 128 + threadIdx.x;   // 0..511
            int mr = flat >> 3;
            int jq = (flat & 7) << 2;
            size_t go = (size_t)(b * N_ + mt + mr) * D_ + h * DH_ + jq;
            *(float4*)(&sk[mr][jq]) = *(const float4*)(pk_ + go);
            *(float4*)(&sv[mr][jq]) = *(const float4*)(v_ + go);
        }
        __syncthreads();
#pragma unroll 2
        for (int m = 0; m < 64; m++) {
            float w = 0.f;
#pragma unroll
            for (int j = 0; j < DH_; j++) w = fmaf(q[j], sk[m][j], w);
            w = fmaxf(w, 0.f);
            w *= w;                 // KP = 2
            s += w;
#pragma unroll
            for (int j = 0; j < DH_; j++) acc[j] = fmaf(w, sv[m][j], acc[j]);
        }
    }
    float inv = 1.f / (s + 1.f);
#pragma unroll
    for (int j = 0; j < DH_; j++)
        cmv[qoff + j] = acc[j] * inv - v_[qoff + j];
}

// ---------------- silu(G) * U ----------------
__global__ void silu_kernel(const float* __restrict__ gu, float* __restrict__ hf) {
    int idx = blockIdx.x * 256 + threadIdx.x;     // (b*N+n)*IN_ + i
    int row = idx >> 10;
    int i   = idx & (IN_ - 1);
    float g = gu[(size_t)row * (2 * IN_) + i];
    float u = gu[(size_t)row * (2 * IN_) + IN_ + i];
    hf[idx] = g / (1.f + expf(-g)) * u;
}

// ---------------- depthwise conv1d over sequence, k=3, pad=1 ----------------
__global__ void conv_kernel(const float* __restrict__ hf, const float* __restrict__ cw,
                            int kidx, float* __restrict__ out) {
    int idx = blockIdx.x * 256 + threadIdx.x;     // (b*N+n)*IN_ + i
    int i   = idx & (IN_ - 1);
    int bn  = idx >> 10;
    int n   = bn & (N_ - 1);
    const float* wp = cw + ((size_t)kidx * IN_ + i) * CK_;
    float a = wp[1] * hf[idx];
    if (n > 0)       a = fmaf(wp[0], hf[idx - IN_], a);
    if (n < N_ - 1)  a = fmaf(wp[2], hf[idx + IN_], a);
    out[idx] = a;
}

// ---------------- halt head: sigmoid(mean_n(Qn) @ halt_w + halt_b) ----------------
__global__ void halt_kernel(const float* __restrict__ qn, const float* __restrict__ hw,
                            const float* __restrict__ hb, float* __restrict__ out, int l4) {
    int b = blockIdx.x;
    int d = threadIdx.x;
    float s = 0.f;
    for (int n = 0; n < N_; n++) s += qn[(size_t)(b * N_ + n) * D_ + d];
    float p = (s * (1.f / N_)) * hw[d];
    float tot = blockReduceSum256(p);
    if (threadIdx.x == 0)
        out[l4 * B_ + b] = 1.f / (1.f + expf(-(tot + hb[0])));
}

// ---------------- host orchestration ----------------
static inline float* symaddr(const void* sym) {
    void* p = nullptr;
    cudaGetSymbolAddress(&p, sym);
    return (float*)p;
}

extern "C" void kernel_launch(void* const* d_in, const int* in_sizes, int n_in,
                              void* d_out, int out_size) {
    const int*   ids   = (const int*)  d_in[0];
    const float* emb   = (const float*)d_in[1];
    const float* pos   = (const float*)d_in[2];
    const float* in_w  = (const float*)d_in[3];
    const float* in_b  = (const float*)d_in[4];
    const float* Wq    = (const float*)d_in[5];
    const float* Wk    = (const float*)d_in[6];
    const float* Wv    = (const float*)d_in[7];
    const float* Wo    = (const float*)d_in[8];
    const float* dts   = (const float*)d_in[9];
    const float* Wup   = (const float*)d_in[10];
    const float* cw    = (const float*)d_in[11];
    const float* Wd    = (const float*)d_in[12];
    const float* n1w   = (const float*)d_in[13];
    const float* n1b   = (const float*)d_in[14];
    const float* n2w   = (const float*)d_in[15];
    const float* n2b   = (const float*)d_in[16];
    const float* fin_w = (const float*)d_in[17];
    const float* fin_b = (const float*)d_in[18];
    const float* haltw = (const float*)d_in[19];
    const float* haltb = (const float*)d_in[20];
    const float* lm_w  = (const float*)d_in[21];

    float* out        = (float*)d_out;
    float* out_logits = out;
    float* out_halts  = out + (size_t)out_size - (size_t)(MAXL_ - TRUNC_) * B_;

    float* pX   = symaddr(g_X);
    float* pQ   = symaddr(g_Q);
    float* pHc  = symaddr(g_Hc);
    float* pPq  = symaddr(g_pq);
    float* pPk  = symaddr(g_pk);
    float* pV   = symaddr(g_v);
    float* pCmv = symaddr(g_cmv);
    float* pHn  = symaddr(g_hn);
    float* pGU  = symaddr(g_gu);
    float* pHf  = symaddr(g_hf);
    float* pHc2 = symaddr(g_hc2);
    float* pQn  = symaddr(g_qn);

    // X = ln(emb[ids] + pos);  Q = X
    embed_kernel<<<BN_, 256>>>(ids, emb, pos, pX);
    ln_kernel<<<BN_, 256>>>(pX, in_w, in_b, nullptr, pX, pQ);

    const dim3 gDD(D_ / BNT, BN_ / BM);             // (4, 32) for D-wide GEMMs
    const dim3 gUP(2 * IN_ / BNT, BN_ / BM);        // (32, 32) for Wup
    const dim3 gLM(V_ / BNT, BN_ / BM);             // (500, 32) for lm head
    const int  ec = (BN_ * IN_) / 256;              // elementwise grid

    for (int l = 0; l < MAXL_; l++) {
        for (int k = 0; k < K_; k++) {
            // Hc = ln(Q; n1) + X
            ln_kernel<<<BN_, 256>>>(pQ, n1w + k * D_, n1b + k * D_, pX, pHc, nullptr);
            // pq = elu(Hc@Wq)+1 ; pk = elu(Hc@Wk)+1 ; v = Hc@Wv
            gemm_kernel<1><<<gDD, 256>>>(pHc, Wq + (size_t)k * D_ * D_, pPq,
                                         BN_, D_, D_, nullptr, nullptr, 0);
            gemm_kernel<1><<<gDD, 256>>>(pHc, Wk + (size_t)k * D_ * D_, pPk,
                                         BN_, D_, D_, nullptr, nullptr, 0);
            gemm_kernel<0><<<gDD, 256>>>(pHc, Wv + (size_t)k * D_ * D_, pV,
                                         BN_, D_, D_, nullptr, nullptr, 0);
            // cmv = (relu(pq pk^T)^2 @ v) / (rowsum + 1) - v
            attn_kernel<<<dim3(B_ * H_, N_ / 128), 128>>>(pPq, pPk, pV, pCmv);
            // Q = Q + softplus(dt_k) * (cmv @ Wo)
            gemm_kernel<2><<<gDD, 256>>>(pCmv, Wo + (size_t)k * D_ * D_, pQ,
                                         BN_, D_, D_, pQ, dts, k);
            // Hn = ln(Q; n2);  GU = Hn @ Wup
            ln_kernel<<<BN_, 256>>>(pQ, n2w + k * D_, n2b + k * D_, nullptr, pHn, nullptr);
            gemm_kernel<0><<<gUP, 256>>>(pHn, Wup + (size_t)k * D_ * 2 * IN_, pGU,
                                         BN_, 2 * IN_, D_, nullptr, nullptr, 0);
            // Hf = silu(G)*U ; Hc2 = depthwise conv3 ; Q = Q + Hc2 @ Wd
            silu_kernel<<<ec, 256>>>(pGU, pHf);
            conv_kernel<<<ec, 256>>>(pHf, cw, k, pHc2);
            gemm_kernel<3><<<gDD, 256>>>(pHc2, Wd + (size_t)k * IN_ * D_, pQ,
                                         BN_, D_, IN_, pQ, nullptr, 0);
        }
        if (l >= TRUNC_) {
            int l4 = l - TRUNC_;
            ln_kernel<<<BN_, 256>>>(pQ, fin_w, fin_b, nullptr, pQn, nullptr);
            halt_kernel<<<B_, 256>>>(pQn, haltw, haltb, out_halts, l4);
            gemm_kernel<0><<<gLM, 256>>>(pQn, lm_w,
                                         out_logits + (size_t)l4 * BN_ * V_,
                                         BN_, V_, D_, nullptr, nullptr, 0);
        }
    }
}